// round 4
// baseline (speedup 1.0000x reference)
#include <cuda_runtime.h>
#include <cuda_fp16.h>

#define NMAX 100000
#define SLOT 64
#define TILE 256

// Scratch (allocation-free): ping-pong node state
__device__ float g_hnf0[NMAX * 64];
__device__ float g_hnf1[NMAX * 64];
__device__ __align__(16) __half g_h16_0[NMAX * 64];
__device__ __align__(16) __half g_h16_1[NMAX * 64];
__device__ int  g_deg[NMAX];
__device__ int2 g_csr[(size_t)NMAX * SLOT];   // (src_byte_offset, w bits)

__device__ __forceinline__ float lrelu(float v) { return v >= 0.f ? v : 0.01f * v; }

// ---- packed f32x2 helpers (sm_103a) ---------------------------------------
__device__ __forceinline__ unsigned long long dup2(float v) {
    unsigned long long r;
    asm("mov.b64 %0, {%1, %1};" : "=l"(r) : "f"(v));
    return r;
}
__device__ __forceinline__ unsigned long long pack2(float a, float b) {
    unsigned long long r;
    asm("mov.b64 %0, {%1, %2};" : "=l"(r) : "f"(a), "f"(b));
    return r;
}
__device__ __forceinline__ void fma2(unsigned long long& acc, unsigned long long a,
                                     unsigned long long b) {
    asm("fma.rn.f32x2 %0, %1, %2, %0;" : "+l"(acc) : "l"(a), "l"(b));
}
__device__ __forceinline__ float2 unpack2(unsigned long long v) {
    float2 f;
    asm("mov.b64 {%0, %1}, %2;" : "=f"(f.x), "=f"(f.y) : "l"(v));
    return f;
}

// ---------------------------------------------------------------------------
// CSR build
// ---------------------------------------------------------------------------
__global__ void zero_deg_kernel(int n) {
    int i = blockIdx.x * blockDim.x + threadIdx.x;
    if (i < n) g_deg[i] = 0;
}

__global__ void fill_csr_kernel(const int* __restrict__ src, const int* __restrict__ dst,
                                const float* __restrict__ w, int ne) {
    int e = blockIdx.x * blockDim.x + threadIdx.x;
    if (e >= ne) return;
    int d = dst[e];
    int slot = atomicAdd(&g_deg[d], 1);
    if (slot < SLOT)
        g_csr[(size_t)d * SLOT + slot] = make_int2(src[e] * 128, __float_as_int(w[e]));
}

// ---------------------------------------------------------------------------
// Encoder + LN(layer 0), THREAD per node; writes buffer 0 (fp32 + fp16)
// ---------------------------------------------------------------------------
__global__ void __launch_bounds__(256, 2)
enc_kernel(const float* __restrict__ x,
           const float* __restrict__ W1, const float* __restrict__ b1,
           const float* __restrict__ W2, const float* __restrict__ b2,
           const float* __restrict__ lg, const float* __restrict__ lb, int n) {
    __shared__ __align__(16) float sW1T[128 * 16];  // [k][j] = W1[j][k]
    __shared__ __align__(16) float sW2[128 * 64];
    __shared__ float sb1[128];
    __shared__ __align__(16) float sb2[64];
    __shared__ float sg[64], sbb[64];
    for (int i = threadIdx.x; i < 2048; i += 256) {
        int j = i >> 7, k = i & 127;
        sW1T[k * 16 + j] = W1[i];
    }
    for (int i = threadIdx.x; i < 8192; i += 256) sW2[i] = W2[i];
    if (threadIdx.x < 128) sb1[threadIdx.x] = b1[threadIdx.x];
    if (threadIdx.x < 64) {
        sb2[threadIdx.x] = b2[threadIdx.x];
        sg[threadIdx.x]  = lg[threadIdx.x];
        sbb[threadIdx.x] = lb[threadIdx.x];
    }
    __syncthreads();

    int i = blockIdx.x * 256 + threadIdx.x;
    if (i >= n) return;

    float xr[16];
    const float4* xp = reinterpret_cast<const float4*>(x + (size_t)i * 16);
    #pragma unroll
    for (int q = 0; q < 4; q++) {
        float4 v = xp[q];
        xr[4 * q] = v.x; xr[4 * q + 1] = v.y; xr[4 * q + 2] = v.z; xr[4 * q + 3] = v.w;
    }

    unsigned long long o2[32];
    const unsigned long long* sb2p = reinterpret_cast<const unsigned long long*>(sb2);
    #pragma unroll
    for (int j = 0; j < 32; j++) o2[j] = sb2p[j];

    #pragma unroll 8
    for (int k = 0; k < 128; k++) {
        const float4* c = reinterpret_cast<const float4*>(sW1T + k * 16);
        float t = sb1[k];
        #pragma unroll
        for (int q = 0; q < 4; q++) {
            float4 wv = c[q];
            t += wv.x * xr[4 * q] + wv.y * xr[4 * q + 1]
               + wv.z * xr[4 * q + 2] + wv.w * xr[4 * q + 3];
        }
        t = lrelu(t);
        unsigned long long tk = dup2(t);
        const ulonglong2* row = reinterpret_cast<const ulonglong2*>(sW2 + k * 64);
        #pragma unroll
        for (int j = 0; j < 16; j++) {
            ulonglong2 p = row[j];
            fma2(o2[2 * j],     tk, p.x);
            fma2(o2[2 * j + 1], tk, p.y);
        }
    }

    float o[64];
    #pragma unroll
    for (int j = 0; j < 32; j++) {
        float2 f = unpack2(o2[j]);
        o[2 * j] = f.x; o[2 * j + 1] = f.y;
    }

    float s = 0.f, sq = 0.f;
    #pragma unroll
    for (int k = 0; k < 64; k++) { s += o[k]; sq += o[k] * o[k]; }
    float mu  = s * (1.f / 64.f);
    float var = sq * (1.f / 64.f) - mu * mu;
    float inv = rsqrtf(var + 1e-5f);

    float4* out4 = reinterpret_cast<float4*>(g_hnf0 + (size_t)i * 64);
    __half2 h2[32];
    #pragma unroll
    for (int k4 = 0; k4 < 16; k4++) {
        float4 v;
        v.x = (o[4 * k4]     - mu) * inv * sg[4 * k4]     + sbb[4 * k4];
        v.y = (o[4 * k4 + 1] - mu) * inv * sg[4 * k4 + 1] + sbb[4 * k4 + 1];
        v.z = (o[4 * k4 + 2] - mu) * inv * sg[4 * k4 + 2] + sbb[4 * k4 + 2];
        v.w = (o[4 * k4 + 3] - mu) * inv * sg[4 * k4 + 3] + sbb[4 * k4 + 3];
        out4[k4] = v;
        h2[2 * k4]     = __floats2half2_rn(v.x, v.y);
        h2[2 * k4 + 1] = __floats2half2_rn(v.z, v.w);
    }
    uint4* d16 = reinterpret_cast<uint4*>(g_h16_0 + (size_t)i * 64);
    const uint4* s16 = reinterpret_cast<const uint4*>(h2);
    #pragma unroll
    for (int q = 0; q < 8; q++) d16[q] = s16[q];
}

// ---------------------------------------------------------------------------
// Fused per-layer kernel:
//   Phase 1 (warp per node): gather msg into shared (fp32, 68-float rows)
//   Phase 2 (thread per node): y = hn@nW + msg@eW + by; o = leaky(y)@mW+mb+hn
//           do_ln ? write LN(o) fp32+fp16 : write o fp32 (decoder input)
// Reads buffer `parity`, writes buffer `1-parity`.
// ---------------------------------------------------------------------------
#define MSG_PITCH 68
__global__ void __launch_bounds__(256, 2)
layer_kernel(const float* __restrict__ nW, const float* __restrict__ nb,
             const float* __restrict__ eW, const float* __restrict__ eb,
             const float* __restrict__ mW, const float* __restrict__ mb,
             const float* __restrict__ lg, const float* __restrict__ lb,
             int do_ln, int parity, int n) {
    extern __shared__ __align__(16) float sm[];
    float* sNW  = sm;            // 2048
    float* sEW  = sm + 2048;     // 2048
    float* sMW  = sm + 4096;     // 2048
    float* sby  = sm + 6144;     // 32
    float* smb  = sm + 6176;     // 64
    float* sg   = sm + 6240;     // 64
    float* sbb  = sm + 6304;     // 64
    float* smsg = sm + 6368;     // 256 * 68

    const float*  hnA   = parity ? g_hnf1 : g_hnf0;
    const __half* hnA16 = parity ? g_h16_1 : g_h16_0;
    float*        hnB   = parity ? g_hnf0 : g_hnf1;
    __half*       hnB16 = parity ? g_h16_0 : g_h16_1;

    for (int i = threadIdx.x; i < 2048; i += 256) {
        sNW[i] = nW[i];
        sEW[i] = eW[i];
        sMW[i] = mW[i];
    }
    if (threadIdx.x < 32) sby[threadIdx.x] = nb[threadIdx.x] + eb[threadIdx.x];
    if (threadIdx.x < 64) {
        smb[threadIdx.x] = mb[threadIdx.x];
        sg[threadIdx.x]  = lg[threadIdx.x];
        sbb[threadIdx.x] = lb[threadIdx.x];
    }

    // ---- Phase 1: gather (warp per node, lane owns channels 2l, 2l+1) ----
    const int lane = threadIdx.x & 31;
    const int warp = threadIdx.x >> 5;
    const int tile0 = blockIdx.x * TILE;
    const char* hb = reinterpret_cast<const char*>(hnA16) + lane * 4;

    for (int ni = warp; ni < TILE; ni += 8) {
        int i = tile0 + ni;
        float ax = 0.f, ay = 0.f;
        if (i < n) {
            int deg = g_deg[i];
            if (deg > SLOT) deg = SLOT;
            const int4* row4 = reinterpret_cast<const int4*>(g_csr + (size_t)i * SLOT);
            int q = 0;
            for (; q + 4 <= deg; q += 4) {
                int4 a = row4[q >> 1];
                int4 b = row4[(q >> 1) + 1];
                __half2 v0 = *reinterpret_cast<const __half2*>(hb + a.x);
                __half2 v1 = *reinterpret_cast<const __half2*>(hb + a.z);
                __half2 v2 = *reinterpret_cast<const __half2*>(hb + b.x);
                __half2 v3 = *reinterpret_cast<const __half2*>(hb + b.z);
                float2 f0 = __half22float2(v0), f1 = __half22float2(v1);
                float2 f2 = __half22float2(v2), f3 = __half22float2(v3);
                float w0 = __int_as_float(a.y), w1 = __int_as_float(a.w);
                float w2 = __int_as_float(b.y), w3 = __int_as_float(b.w);
                ax += w0 * f0.x + w1 * f1.x + w2 * f2.x + w3 * f3.x;
                ay += w0 * f0.y + w1 * f1.y + w2 * f2.y + w3 * f3.y;
            }
            for (; q + 2 <= deg; q += 2) {
                int4 a = row4[q >> 1];
                __half2 v0 = *reinterpret_cast<const __half2*>(hb + a.x);
                __half2 v1 = *reinterpret_cast<const __half2*>(hb + a.z);
                float2 f0 = __half22float2(v0), f1 = __half22float2(v1);
                float w0 = __int_as_float(a.y), w1 = __int_as_float(a.w);
                ax += w0 * f0.x + w1 * f1.x;
                ay += w0 * f0.y + w1 * f1.y;
            }
            if (q < deg) {
                int2 e = reinterpret_cast<const int2*>(row4)[q];
                __half2 v = *reinterpret_cast<const __half2*>(hb + e.x);
                float2 f = __half22float2(v);
                float w = __int_as_float(e.y);
                ax += w * f.x;
                ay += w * f.y;
            }
        }
        *reinterpret_cast<float2*>(smsg + ni * MSG_PITCH + 2 * lane) = make_float2(ax, ay);
    }
    __syncthreads();

    // ---- Phase 2: update (thread per node) ----
    int i = tile0 + threadIdx.x;
    if (i >= n) return;

    const float4* hn4 = reinterpret_cast<const float4*>(hnA + (size_t)i * 64);
    const float4* m4  = reinterpret_cast<const float4*>(smsg + threadIdx.x * MSG_PITCH);

    unsigned long long y2[16];
    const unsigned long long* sby2 = reinterpret_cast<const unsigned long long*>(sby);
    #pragma unroll
    for (int j = 0; j < 16; j++) y2[j] = sby2[j];

    // y += hn @ nW
    const ulonglong2* NW2 = reinterpret_cast<const ulonglong2*>(sNW);
    #pragma unroll
    for (int k4 = 0; k4 < 16; k4++) {
        float4 hv = hn4[k4];
        float hc[4] = {hv.x, hv.y, hv.z, hv.w};
        #pragma unroll
        for (int c = 0; c < 4; c++) {
            unsigned long long hk = dup2(hc[c]);
            const ulonglong2* row = NW2 + (k4 * 4 + c) * 8;
            #pragma unroll
            for (int j = 0; j < 8; j++) {
                ulonglong2 p = row[j];
                fma2(y2[2 * j],     hk, p.x);
                fma2(y2[2 * j + 1], hk, p.y);
            }
        }
    }

    // y += msg @ eW  (msg from shared)
    const ulonglong2* EW2 = reinterpret_cast<const ulonglong2*>(sEW);
    #pragma unroll
    for (int k4 = 0; k4 < 16; k4++) {
        float4 mv = m4[k4];
        float mc[4] = {mv.x, mv.y, mv.z, mv.w};
        #pragma unroll
        for (int c = 0; c < 4; c++) {
            unsigned long long mk = dup2(mc[c]);
            const ulonglong2* row = EW2 + (k4 * 4 + c) * 8;
            #pragma unroll
            for (int j = 0; j < 8; j++) {
                ulonglong2 p = row[j];
                fma2(y2[2 * j],     mk, p.x);
                fma2(y2[2 * j + 1], mk, p.y);
            }
        }
    }

    float z[32];
    #pragma unroll
    for (int j = 0; j < 16; j++) {
        float2 f = unpack2(y2[j]);
        z[2 * j]     = lrelu(f.x);
        z[2 * j + 1] = lrelu(f.y);
    }

    unsigned long long o2[32];
    const unsigned long long* smb2 = reinterpret_cast<const unsigned long long*>(smb);
    #pragma unroll
    for (int j = 0; j < 32; j++) o2[j] = smb2[j];

    const ulonglong2* MW2 = reinterpret_cast<const ulonglong2*>(sMW);
    #pragma unroll
    for (int k = 0; k < 32; k++) {
        unsigned long long zk = dup2(z[k]);
        const ulonglong2* row = MW2 + k * 16;
        #pragma unroll
        for (int j = 0; j < 16; j++) {
            ulonglong2 p = row[j];
            fma2(o2[2 * j],     zk, p.x);
            fma2(o2[2 * j + 1], zk, p.y);
        }
    }

    float o[64];
    #pragma unroll
    for (int j = 0; j < 32; j++) {
        float2 f = unpack2(o2[j]);
        o[2 * j] = f.x; o[2 * j + 1] = f.y;
    }
    #pragma unroll
    for (int k4 = 0; k4 < 16; k4++) {
        float4 hv = hn4[k4];
        o[4 * k4]     += hv.x;
        o[4 * k4 + 1] += hv.y;
        o[4 * k4 + 2] += hv.z;
        o[4 * k4 + 3] += hv.w;
    }

    if (do_ln) {
        float s = 0.f, sq = 0.f;
        #pragma unroll
        for (int k = 0; k < 64; k++) { s += o[k]; sq += o[k] * o[k]; }
        float mu  = s * (1.f / 64.f);
        float var = sq * (1.f / 64.f) - mu * mu;
        float inv = rsqrtf(var + 1e-5f);
        float4* out4 = reinterpret_cast<float4*>(hnB + (size_t)i * 64);
        __half2 h2[32];
        #pragma unroll
        for (int k4 = 0; k4 < 16; k4++) {
            float4 v;
            v.x = (o[4 * k4]     - mu) * inv * sg[4 * k4]     + sbb[4 * k4];
            v.y = (o[4 * k4 + 1] - mu) * inv * sg[4 * k4 + 1] + sbb[4 * k4 + 1];
            v.z = (o[4 * k4 + 2] - mu) * inv * sg[4 * k4 + 2] + sbb[4 * k4 + 2];
            v.w = (o[4 * k4 + 3] - mu) * inv * sg[4 * k4 + 3] + sbb[4 * k4 + 3];
            out4[k4] = v;
            h2[2 * k4]     = __floats2half2_rn(v.x, v.y);
            h2[2 * k4 + 1] = __floats2half2_rn(v.z, v.w);
        }
        uint4* d16 = reinterpret_cast<uint4*>(hnB16 + (size_t)i * 64);
        const uint4* s16 = reinterpret_cast<const uint4*>(h2);
        #pragma unroll
        for (int q = 0; q < 8; q++) d16[q] = s16[q];
    } else {
        float4* out4 = reinterpret_cast<float4*>(hnB + (size_t)i * 64);
        #pragma unroll
        for (int k4 = 0; k4 < 16; k4++) {
            float4 v;
            v.x = o[4 * k4];     v.y = o[4 * k4 + 1];
            v.z = o[4 * k4 + 2]; v.w = o[4 * k4 + 3];
            out4[k4] = v;
        }
    }
}

// ---------------------------------------------------------------------------
// Decoder, THREAD per node: out = leaky(h@W1+b1)@W2 + b2 (64->24->3); reads buf0
// ---------------------------------------------------------------------------
__global__ void __launch_bounds__(256, 2)
dec_kernel(const float* __restrict__ W1, const float* __restrict__ b1,
           const float* __restrict__ W2, const float* __restrict__ b2,
           float* __restrict__ out, int n) {
    __shared__ __align__(16) float sW1T[24 * 64];  // [j][k] = W1[k][j]
    __shared__ float sW2T[3 * 24];
    __shared__ float sb1[24];
    __shared__ float sb2v[3];
    for (int i = threadIdx.x; i < 1536; i += 256) {
        int k = i / 24, j = i % 24;
        sW1T[j * 64 + k] = W1[i];
    }
    if (threadIdx.x < 72) {
        int j = threadIdx.x / 3, c = threadIdx.x % 3;
        sW2T[c * 24 + j] = W2[threadIdx.x];
    }
    if (threadIdx.x < 24) sb1[threadIdx.x] = b1[threadIdx.x];
    if (threadIdx.x < 3)  sb2v[threadIdx.x] = b2[threadIdx.x];
    __syncthreads();

    int i = blockIdx.x * 256 + threadIdx.x;
    if (i >= n) return;

    unsigned long long hp[32];
    const float4* h4 = reinterpret_cast<const float4*>(g_hnf0 + (size_t)i * 64);
    #pragma unroll
    for (int q = 0; q < 16; q++) {
        float4 v = h4[q];
        hp[2 * q]     = pack2(v.x, v.y);
        hp[2 * q + 1] = pack2(v.z, v.w);
    }

    float t[24];
    #pragma unroll
    for (int j = 0; j < 24; j++) {
        unsigned long long acc = 0ULL;
        const ulonglong2* row = reinterpret_cast<const ulonglong2*>(sW1T + j * 64);
        #pragma unroll
        for (int m = 0; m < 16; m++) {
            ulonglong2 p = row[m];
            fma2(acc, hp[2 * m],     p.x);
            fma2(acc, hp[2 * m + 1], p.y);
        }
        float2 f = unpack2(acc);
        t[j] = lrelu(sb1[j] + f.x + f.y);
    }

    #pragma unroll
    for (int c = 0; c < 3; c++) {
        float o = sb2v[c];
        #pragma unroll
        for (int j = 0; j < 24; j++) o += t[j] * sW2T[c * 24 + j];
        out[(size_t)i * 3 + c] = o;
    }
}

// ---------------------------------------------------------------------------
extern "C" void kernel_launch(void* const* d_in, const int* in_sizes, int n_in,
                              void* d_out, int out_size) {
    const float* x       = (const float*)d_in[0];
    // d_in[1] = pos (unused by reference)
    const int*   esrc    = (const int*)  d_in[2];
    const int*   edst    = (const int*)  d_in[3];
    const float* ew      = (const float*)d_in[4];
    const float* enc_W1  = (const float*)d_in[5];
    const float* enc_b1  = (const float*)d_in[6];
    const float* enc_W2  = (const float*)d_in[7];
    const float* enc_b2  = (const float*)d_in[8];
    const float* dec_W1  = (const float*)d_in[9];
    const float* dec_b1  = (const float*)d_in[10];
    const float* dec_W2  = (const float*)d_in[11];
    const float* dec_b2  = (const float*)d_in[12];
    const float* ln_g    = (const float*)d_in[13];
    const float* ln_b    = (const float*)d_in[14];
    const float* node_W  = (const float*)d_in[15];
    const float* node_b  = (const float*)d_in[16];
    const float* edge_W  = (const float*)d_in[17];
    const float* edge_b  = (const float*)d_in[18];
    const float* mlp_W   = (const float*)d_in[19];
    const float* mlp_b   = (const float*)d_in[20];

    const int n  = in_sizes[0] / 16;   // 100000 nodes
    const int ne = in_sizes[2];        // 1200000 edges

    const int nb = (n + 255) / 256;
    const int fe = (ne + 255) / 256;
    const int layer_smem = (6368 + TILE * MSG_PITCH) * 4;  // ~95 KB

    static int attr_done = 0;
    if (!attr_done) {
        cudaFuncSetAttribute(layer_kernel,
                             cudaFuncAttributeMaxDynamicSharedMemorySize, layer_smem);
        attr_done = 1;
    }

    zero_deg_kernel<<<nb, 256>>>(n);
    fill_csr_kernel<<<fe, 256>>>(esrc, edst, ew, ne);

    enc_kernel<<<nb, 256>>>(x, enc_W1, enc_b1, enc_W2, enc_b2, ln_g, ln_b, n);

    for (int l = 0; l < 4; l++) {
        const float* next_g = ln_g + (l + 1 < 4 ? (l + 1) * 64 : 0);
        const float* next_b = ln_b + (l + 1 < 4 ? (l + 1) * 64 : 0);
        layer_kernel<<<nb, 256, layer_smem>>>(
            node_W + l * 2048, node_b + l * 32,
            edge_W + l * 2048, edge_b + l * 32,
            mlp_W  + l * 2048, mlp_b  + l * 64,
            next_g, next_b,
            (l < 3) ? 1 : 0, l & 1, n);
    }

    dec_kernel<<<nb, 256>>>(dec_W1, dec_b1, dec_W2, dec_b2, (float*)d_out, n);
}

// round 5
// speedup vs baseline: 1.3682x; 1.3682x over previous
#include <cuda_runtime.h>
#include <cuda_fp16.h>

#define NMAX 100000
#define SLOT 64

// Scratch (allocation-free)
__device__ float g_hn[NMAX * 64];                    // LN'd state fp32
__device__ __align__(16) __half g_hn16[NMAX * 64];   // LN'd state fp16 (gather operand)
__device__ float g_msg[NMAX * 64];                   // gathered messages
__device__ int  g_deg[NMAX];
__device__ int2 g_csr[(size_t)NMAX * SLOT];          // (src byte offset, w bits)

__device__ __forceinline__ float lrelu(float v) { return v >= 0.f ? v : 0.01f * v; }

// ---- packed f32x2 helpers (sm_103a) ---------------------------------------
__device__ __forceinline__ unsigned long long dup2(float v) {
    unsigned long long r;
    asm("mov.b64 %0, {%1, %1};" : "=l"(r) : "f"(v));
    return r;
}
__device__ __forceinline__ unsigned long long pack2(float a, float b) {
    unsigned long long r;
    asm("mov.b64 %0, {%1, %2};" : "=l"(r) : "f"(a), "f"(b));
    return r;
}
__device__ __forceinline__ void fma2(unsigned long long& acc, unsigned long long a,
                                     unsigned long long b) {
    asm("fma.rn.f32x2 %0, %1, %2, %0;" : "+l"(acc) : "l"(a), "l"(b));
}
__device__ __forceinline__ float2 unpack2(unsigned long long v) {
    float2 f;
    asm("mov.b64 {%0, %1}, %2;" : "=f"(f.x), "=f"(f.y) : "l"(v));
    return f;
}

// ---------------------------------------------------------------------------
// CSR fill (g_deg zeroed by enc_kernel, which runs first)
// ---------------------------------------------------------------------------
__global__ void fill_csr_kernel(const int* __restrict__ src, const int* __restrict__ dst,
                                const float* __restrict__ w, int ne) {
    int e = blockIdx.x * blockDim.x + threadIdx.x;
    if (e >= ne) return;
    int d = dst[e];
    int slot = atomicAdd(&g_deg[d], 1);
    if (slot < SLOT)
        g_csr[(size_t)d * SLOT + slot] = make_int2(src[e] * 128, __float_as_int(w[e]));
}

// ---------------------------------------------------------------------------
// Encoder + LN(layer 0), THREAD per node. Also zeroes g_deg for fill_csr.
// ---------------------------------------------------------------------------
__global__ void __launch_bounds__(256, 2)
enc_kernel(const float* __restrict__ x,
           const float* __restrict__ W1, const float* __restrict__ b1,
           const float* __restrict__ W2, const float* __restrict__ b2,
           const float* __restrict__ lg, const float* __restrict__ lb, int n) {
    __shared__ __align__(16) float sW1T[128 * 16];  // [k][j] = W1[j][k]
    __shared__ __align__(16) float sW2[128 * 64];
    __shared__ float sb1[128];
    __shared__ __align__(16) float sb2[64];
    __shared__ float sg[64], sbb[64];
    for (int i = threadIdx.x; i < 2048; i += 256) {
        int j = i >> 7, k = i & 127;
        sW1T[k * 16 + j] = W1[i];
    }
    for (int i = threadIdx.x; i < 8192; i += 256) sW2[i] = W2[i];
    if (threadIdx.x < 128) sb1[threadIdx.x] = b1[threadIdx.x];
    if (threadIdx.x < 64) {
        sb2[threadIdx.x] = b2[threadIdx.x];
        sg[threadIdx.x]  = lg[threadIdx.x];
        sbb[threadIdx.x] = lb[threadIdx.x];
    }
    __syncthreads();

    int i = blockIdx.x * 256 + threadIdx.x;
    if (i >= n) return;
    g_deg[i] = 0;   // prepare for fill_csr_kernel

    float xr[16];
    const float4* xp = reinterpret_cast<const float4*>(x + (size_t)i * 16);
    #pragma unroll
    for (int q = 0; q < 4; q++) {
        float4 v = xp[q];
        xr[4 * q] = v.x; xr[4 * q + 1] = v.y; xr[4 * q + 2] = v.z; xr[4 * q + 3] = v.w;
    }

    unsigned long long o2[32];
    const unsigned long long* sb2p = reinterpret_cast<const unsigned long long*>(sb2);
    #pragma unroll
    for (int j = 0; j < 32; j++) o2[j] = sb2p[j];

    #pragma unroll 8
    for (int k = 0; k < 128; k++) {
        const float4* c = reinterpret_cast<const float4*>(sW1T + k * 16);
        float t = sb1[k];
        #pragma unroll
        for (int q = 0; q < 4; q++) {
            float4 wv = c[q];
            t += wv.x * xr[4 * q] + wv.y * xr[4 * q + 1]
               + wv.z * xr[4 * q + 2] + wv.w * xr[4 * q + 3];
        }
        t = lrelu(t);
        unsigned long long tk = dup2(t);
        const ulonglong2* row = reinterpret_cast<const ulonglong2*>(sW2 + k * 64);
        #pragma unroll
        for (int j = 0; j < 16; j++) {
            ulonglong2 p = row[j];
            fma2(o2[2 * j],     tk, p.x);
            fma2(o2[2 * j + 1], tk, p.y);
        }
    }

    float o[64];
    #pragma unroll
    for (int j = 0; j < 32; j++) {
        float2 f = unpack2(o2[j]);
        o[2 * j] = f.x; o[2 * j + 1] = f.y;
    }

    float s = 0.f, sq = 0.f;
    #pragma unroll
    for (int k = 0; k < 64; k++) { s += o[k]; sq += o[k] * o[k]; }
    float mu  = s * (1.f / 64.f);
    float var = sq * (1.f / 64.f) - mu * mu;
    float inv = rsqrtf(var + 1e-5f);

    float4* out4 = reinterpret_cast<float4*>(g_hn + (size_t)i * 64);
    __half2 h2[32];
    #pragma unroll
    for (int k4 = 0; k4 < 16; k4++) {
        float4 v;
        v.x = (o[4 * k4]     - mu) * inv * sg[4 * k4]     + sbb[4 * k4];
        v.y = (o[4 * k4 + 1] - mu) * inv * sg[4 * k4 + 1] + sbb[4 * k4 + 1];
        v.z = (o[4 * k4 + 2] - mu) * inv * sg[4 * k4 + 2] + sbb[4 * k4 + 2];
        v.w = (o[4 * k4 + 3] - mu) * inv * sg[4 * k4 + 3] + sbb[4 * k4 + 3];
        out4[k4] = v;
        h2[2 * k4]     = __floats2half2_rn(v.x, v.y);
        h2[2 * k4 + 1] = __floats2half2_rn(v.z, v.w);
    }
    uint4* d16 = reinterpret_cast<uint4*>(g_hn16 + (size_t)i * 64);
    const uint4* s16 = reinterpret_cast<const uint4*>(h2);
    #pragma unroll
    for (int q = 0; q < 8; q++) d16[q] = s16[q];
}

// ---------------------------------------------------------------------------
// CSR gather: msg[i] = sum_e w_e * hn16[src_e]. Warp per node, lane = channel
// pair. Byte-offset CSR + int4 meta loads (2 edges / 16 B) + 4-edge unroll.
// ---------------------------------------------------------------------------
__global__ void gather_kernel(int n) {
    const int lane = threadIdx.x & 31;
    int i = (blockIdx.x * blockDim.x + threadIdx.x) >> 5;
    if (i >= n) return;

    int deg = g_deg[i];
    if (deg > SLOT) deg = SLOT;
    const int4* row4 = reinterpret_cast<const int4*>(g_csr + (size_t)i * SLOT);
    const char* hb = reinterpret_cast<const char*>(g_hn16) + lane * 4;

    float ax = 0.f, ay = 0.f;
    int q = 0;
    for (; q + 4 <= deg; q += 4) {
        int4 a = row4[q >> 1];
        int4 b = row4[(q >> 1) + 1];
        __half2 v0 = *reinterpret_cast<const __half2*>(hb + a.x);
        __half2 v1 = *reinterpret_cast<const __half2*>(hb + a.z);
        __half2 v2 = *reinterpret_cast<const __half2*>(hb + b.x);
        __half2 v3 = *reinterpret_cast<const __half2*>(hb + b.z);
        float2 f0 = __half22float2(v0), f1 = __half22float2(v1);
        float2 f2 = __half22float2(v2), f3 = __half22float2(v3);
        float w0 = __int_as_float(a.y), w1 = __int_as_float(a.w);
        float w2 = __int_as_float(b.y), w3 = __int_as_float(b.w);
        ax += w0 * f0.x + w1 * f1.x + w2 * f2.x + w3 * f3.x;
        ay += w0 * f0.y + w1 * f1.y + w2 * f2.y + w3 * f3.y;
    }
    for (; q + 2 <= deg; q += 2) {
        int4 a = row4[q >> 1];
        __half2 v0 = *reinterpret_cast<const __half2*>(hb + a.x);
        __half2 v1 = *reinterpret_cast<const __half2*>(hb + a.z);
        float2 f0 = __half22float2(v0), f1 = __half22float2(v1);
        float w0 = __int_as_float(a.y), w1 = __int_as_float(a.w);
        ax += w0 * f0.x + w1 * f1.x;
        ay += w0 * f0.y + w1 * f1.y;
    }
    if (q < deg) {
        int2 e = reinterpret_cast<const int2*>(row4)[q];
        __half2 v = *reinterpret_cast<const __half2*>(hb + e.x);
        float2 f = __half22float2(v);
        float w = __int_as_float(e.y);
        ax += w * f.x;
        ay += w * f.y;
    }
    reinterpret_cast<float2*>(g_msg)[(size_t)i * 32 + lane] = make_float2(ax, ay);
}

// ---------------------------------------------------------------------------
// Shared body: y = hn@nW + msg@eW + by; o = leaky(y)@mW + mb + hn  (o in regs)
// ---------------------------------------------------------------------------
__device__ __forceinline__ void node_update_body(
    int i, const float* sNW, const float* sEW, const float* sMW,
    const float* sby, const float* smb, float (&o)[64]) {
    const float4* hn4 = reinterpret_cast<const float4*>(g_hn + (size_t)i * 64);
    const float4* m4  = reinterpret_cast<const float4*>(g_msg + (size_t)i * 64);

    unsigned long long y2[16];
    const unsigned long long* sby2 = reinterpret_cast<const unsigned long long*>(sby);
    #pragma unroll
    for (int j = 0; j < 16; j++) y2[j] = sby2[j];

    const ulonglong2* NW2 = reinterpret_cast<const ulonglong2*>(sNW);
    #pragma unroll
    for (int k4 = 0; k4 < 16; k4++) {
        float4 hv = hn4[k4];
        float hc[4] = {hv.x, hv.y, hv.z, hv.w};
        #pragma unroll
        for (int c = 0; c < 4; c++) {
            unsigned long long hk = dup2(hc[c]);
            const ulonglong2* row = NW2 + (k4 * 4 + c) * 8;
            #pragma unroll
            for (int j = 0; j < 8; j++) {
                ulonglong2 p = row[j];
                fma2(y2[2 * j],     hk, p.x);
                fma2(y2[2 * j + 1], hk, p.y);
            }
        }
    }

    const ulonglong2* EW2 = reinterpret_cast<const ulonglong2*>(sEW);
    #pragma unroll
    for (int k4 = 0; k4 < 16; k4++) {
        float4 mv = m4[k4];
        float mc[4] = {mv.x, mv.y, mv.z, mv.w};
        #pragma unroll
        for (int c = 0; c < 4; c++) {
            unsigned long long mk = dup2(mc[c]);
            const ulonglong2* row = EW2 + (k4 * 4 + c) * 8;
            #pragma unroll
            for (int j = 0; j < 8; j++) {
                ulonglong2 p = row[j];
                fma2(y2[2 * j],     mk, p.x);
                fma2(y2[2 * j + 1], mk, p.y);
            }
        }
    }

    float z[32];
    #pragma unroll
    for (int j = 0; j < 16; j++) {
        float2 f = unpack2(y2[j]);
        z[2 * j]     = lrelu(f.x);
        z[2 * j + 1] = lrelu(f.y);
    }

    unsigned long long o2[32];
    const unsigned long long* smb2 = reinterpret_cast<const unsigned long long*>(smb);
    #pragma unroll
    for (int j = 0; j < 32; j++) o2[j] = smb2[j];

    const ulonglong2* MW2 = reinterpret_cast<const ulonglong2*>(sMW);
    #pragma unroll
    for (int k = 0; k < 32; k++) {
        unsigned long long zk = dup2(z[k]);
        const ulonglong2* row = MW2 + k * 16;
        #pragma unroll
        for (int j = 0; j < 16; j++) {
            ulonglong2 p = row[j];
            fma2(o2[2 * j],     zk, p.x);
            fma2(o2[2 * j + 1], zk, p.y);
        }
    }

    #pragma unroll
    for (int j = 0; j < 32; j++) {
        float2 f = unpack2(o2[j]);
        o[2 * j] = f.x; o[2 * j + 1] = f.y;
    }
    #pragma unroll
    for (int k4 = 0; k4 < 16; k4++) {
        float4 hv = hn4[k4];
        o[4 * k4]     += hv.x;
        o[4 * k4 + 1] += hv.y;
        o[4 * k4 + 2] += hv.z;
        o[4 * k4 + 3] += hv.w;
    }
}

// ---------------------------------------------------------------------------
// Layers 0-2: update + LN -> writes g_hn / g_hn16 in place
// ---------------------------------------------------------------------------
__global__ void __launch_bounds__(256, 2)
update_kernel(const float* __restrict__ nW, const float* __restrict__ nb,
              const float* __restrict__ eW, const float* __restrict__ eb,
              const float* __restrict__ mW, const float* __restrict__ mb,
              const float* __restrict__ lg, const float* __restrict__ lb, int n) {
    __shared__ __align__(16) float sNW[64 * 32];
    __shared__ __align__(16) float sEW[64 * 32];
    __shared__ __align__(16) float sMW[32 * 64];
    __shared__ __align__(16) float sby[32];
    __shared__ __align__(16) float smb[64];
    __shared__ float sg[64], sbb[64];
    for (int i = threadIdx.x; i < 2048; i += 256) {
        sNW[i] = nW[i];
        sEW[i] = eW[i];
        sMW[i] = mW[i];
    }
    if (threadIdx.x < 32) sby[threadIdx.x] = nb[threadIdx.x] + eb[threadIdx.x];
    if (threadIdx.x < 64) {
        smb[threadIdx.x] = mb[threadIdx.x];
        sg[threadIdx.x]  = lg[threadIdx.x];
        sbb[threadIdx.x] = lb[threadIdx.x];
    }
    __syncthreads();

    int i = blockIdx.x * 256 + threadIdx.x;
    if (i >= n) return;

    float o[64];
    node_update_body(i, sNW, sEW, sMW, sby, smb, o);

    float s = 0.f, sq = 0.f;
    #pragma unroll
    for (int k = 0; k < 64; k++) { s += o[k]; sq += o[k] * o[k]; }
    float mu  = s * (1.f / 64.f);
    float var = sq * (1.f / 64.f) - mu * mu;
    float inv = rsqrtf(var + 1e-5f);

    float4* out4 = reinterpret_cast<float4*>(g_hn + (size_t)i * 64);
    __half2 h2[32];
    #pragma unroll
    for (int k4 = 0; k4 < 16; k4++) {
        float4 v;
        v.x = (o[4 * k4]     - mu) * inv * sg[4 * k4]     + sbb[4 * k4];
        v.y = (o[4 * k4 + 1] - mu) * inv * sg[4 * k4 + 1] + sbb[4 * k4 + 1];
        v.z = (o[4 * k4 + 2] - mu) * inv * sg[4 * k4 + 2] + sbb[4 * k4 + 2];
        v.w = (o[4 * k4 + 3] - mu) * inv * sg[4 * k4 + 3] + sbb[4 * k4 + 3];
        out4[k4] = v;
        h2[2 * k4]     = __floats2half2_rn(v.x, v.y);
        h2[2 * k4 + 1] = __floats2half2_rn(v.z, v.w);
    }
    uint4* d16 = reinterpret_cast<uint4*>(g_hn16 + (size_t)i * 64);
    const uint4* s16 = reinterpret_cast<const uint4*>(h2);
    #pragma unroll
    for (int q = 0; q < 8; q++) d16[q] = s16[q];
}

// ---------------------------------------------------------------------------
// Layer 3 fused with decoder: out = leaky(o@dW1+db1)@dW2 + db2, no g_h traffic
// ---------------------------------------------------------------------------
__global__ void __launch_bounds__(256)
update_dec_kernel(const float* __restrict__ nW, const float* __restrict__ nb,
                  const float* __restrict__ eW, const float* __restrict__ eb,
                  const float* __restrict__ mW, const float* __restrict__ mb,
                  const float* __restrict__ dW1, const float* __restrict__ db1,
                  const float* __restrict__ dW2, const float* __restrict__ db2,
                  float* __restrict__ out, int n) {
    __shared__ __align__(16) float sNW[64 * 32];
    __shared__ __align__(16) float sEW[64 * 32];
    __shared__ __align__(16) float sMW[32 * 64];
    __shared__ __align__(16) float sby[32];
    __shared__ __align__(16) float smb[64];
    __shared__ __align__(16) float sW1T[24 * 64];  // [j][k] = dW1[k][j]
    __shared__ float sW2T[3 * 24];
    __shared__ float sdb1[24];
    __shared__ float sdb2[3];
    for (int i = threadIdx.x; i < 2048; i += 256) {
        sNW[i] = nW[i];
        sEW[i] = eW[i];
        sMW[i] = mW[i];
    }
    for (int i = threadIdx.x; i < 1536; i += 256) {
        int k = i / 24, j = i % 24;
        sW1T[j * 64 + k] = dW1[i];
    }
    if (threadIdx.x < 72) {
        int j = threadIdx.x / 3, c = threadIdx.x % 3;
        sW2T[c * 24 + j] = dW2[threadIdx.x];
    }
    if (threadIdx.x < 32) sby[threadIdx.x] = nb[threadIdx.x] + eb[threadIdx.x];
    if (threadIdx.x < 64) smb[threadIdx.x] = mb[threadIdx.x];
    if (threadIdx.x < 24) sdb1[threadIdx.x] = db1[threadIdx.x];
    if (threadIdx.x < 3)  sdb2[threadIdx.x] = db2[threadIdx.x];
    __syncthreads();

    int i = blockIdx.x * 256 + threadIdx.x;
    if (i >= n) return;

    float o[64];
    node_update_body(i, sNW, sEW, sMW, sby, smb, o);

    // decoder: 64 -> 24 -> 3
    unsigned long long hp[32];
    #pragma unroll
    for (int q = 0; q < 32; q++) hp[q] = pack2(o[2 * q], o[2 * q + 1]);

    float t[24];
    #pragma unroll
    for (int j = 0; j < 24; j++) {
        unsigned long long acc = 0ULL;
        const ulonglong2* row = reinterpret_cast<const ulonglong2*>(sW1T + j * 64);
        #pragma unroll
        for (int m = 0; m < 16; m++) {
            ulonglong2 p = row[m];
            fma2(acc, hp[2 * m],     p.x);
            fma2(acc, hp[2 * m + 1], p.y);
        }
        float2 f = unpack2(acc);
        t[j] = lrelu(sdb1[j] + f.x + f.y);
    }

    #pragma unroll
    for (int c = 0; c < 3; c++) {
        float oo = sdb2[c];
        #pragma unroll
        for (int j = 0; j < 24; j++) oo += t[j] * sW2T[c * 24 + j];
        out[(size_t)i * 3 + c] = oo;
    }
}

// ---------------------------------------------------------------------------
extern "C" void kernel_launch(void* const* d_in, const int* in_sizes, int n_in,
                              void* d_out, int out_size) {
    const float* x       = (const float*)d_in[0];
    // d_in[1] = pos (unused by reference)
    const int*   esrc    = (const int*)  d_in[2];
    const int*   edst    = (const int*)  d_in[3];
    const float* ew      = (const float*)d_in[4];
    const float* enc_W1  = (const float*)d_in[5];
    const float* enc_b1  = (const float*)d_in[6];
    const float* enc_W2  = (const float*)d_in[7];
    const float* enc_b2  = (const float*)d_in[8];
    const float* dec_W1  = (const float*)d_in[9];
    const float* dec_b1  = (const float*)d_in[10];
    const float* dec_W2  = (const float*)d_in[11];
    const float* dec_b2  = (const float*)d_in[12];
    const float* ln_g    = (const float*)d_in[13];
    const float* ln_b    = (const float*)d_in[14];
    const float* node_W  = (const float*)d_in[15];
    const float* node_b  = (const float*)d_in[16];
    const float* edge_W  = (const float*)d_in[17];
    const float* edge_b  = (const float*)d_in[18];
    const float* mlp_W   = (const float*)d_in[19];
    const float* mlp_b   = (const float*)d_in[20];

    const int n  = in_sizes[0] / 16;   // 100000 nodes
    const int ne = in_sizes[2];        // 1200000 edges

    const int nb = (n + 255) / 256;
    const int fe = (ne + 255) / 256;
    const int ga = (int)(((long long)n * 32 + 255) / 256);

    // enc zeroes g_deg; fill must follow enc
    enc_kernel<<<nb, 256>>>(x, enc_W1, enc_b1, enc_W2, enc_b2, ln_g, ln_b, n);
    fill_csr_kernel<<<fe, 256>>>(esrc, edst, ew, ne);

    for (int l = 0; l < 3; l++) {
        gather_kernel<<<ga, 256>>>(n);
        update_kernel<<<nb, 256>>>(node_W + l * 2048, node_b + l * 32,
                                   edge_W + l * 2048, edge_b + l * 32,
                                   mlp_W  + l * 2048, mlp_b  + l * 64,
                                   ln_g + (l + 1) * 64, ln_b + (l + 1) * 64, n);
    }

    gather_kernel<<<ga, 256>>>(n);
    update_dec_kernel<<<nb, 256>>>(node_W + 3 * 2048, node_b + 3 * 32,
                                   edge_W + 3 * 2048, edge_b + 3 * 32,
                                   mlp_W  + 3 * 2048, mlp_b  + 3 * 64,
                                   dec_W1, dec_b1, dec_W2, dec_b2,
                                   (float*)d_out, n);
}